// round 9
// baseline (speedup 1.0000x reference)
#include <cuda_runtime.h>
#include <cstdint>
#include <math.h>

#define NB   4
#define S    2048
#define D    1024
#define NS   (NB*S)               // 8192

// ---------------- device scratch (split planes stored as float2{t0,t1}) ------
__device__ float2 g_qs  [(size_t)NS*D];    // 64 MB  q split
__device__ float2 g_ks  [(size_t)NS*D];    // 64 MB  k split
__device__ float2 g_vs  [(size_t)NS*D];    // 64 MB  v split
__device__ float2 g_wqw [(size_t)D*D];     // 8 MB   WQ split
__device__ float2 g_wkw [(size_t)D*D];     // 8 MB   WK split
__device__ float2 g_wvw [(size_t)D*D];     // 8 MB   WV split
__device__ float2 g_wqs [(size_t)NS*D];    // 64 MB  wq proj split
__device__ float2 g_wks [(size_t)NS*D];    // 64 MB  wk proj split
__device__ float2 g_wvts[(size_t)D*NS];    // 64 MB  wv^T proj split [o][n*S+s]
__device__ float  g_p   [(size_t)NB*S*S];  // 64 MB  scores P[n][k][q] fp32
__device__ float2 g_pts [(size_t)NB*S*S];  // 128 MB softmaxed P^T split [n][q][k]

// ---------------- helpers ----------------
__device__ __forceinline__ uint32_t f2tf32(float f) {
    uint32_t r;
    asm("cvt.rna.tf32.f32 %0, %1;" : "=r"(r) : "f"(f));
    return r;
}
__device__ __forceinline__ float2 split2(float f) {
    uint32_t t0 = f2tf32(f);
    uint32_t t1 = f2tf32(f - __uint_as_float(t0));
    return make_float2(__uint_as_float(t0), __uint_as_float(t1));
}
__device__ __forceinline__ void mma_tf32(float* c, const uint32_t* a, const uint32_t* b) {
    asm volatile(
        "mma.sync.aligned.m16n8k8.row.col.f32.tf32.tf32.f32 "
        "{%0,%1,%2,%3}, {%4,%5,%6,%7}, {%8,%9}, {%0,%1,%2,%3};"
        : "+f"(c[0]), "+f"(c[1]), "+f"(c[2]), "+f"(c[3])
        : "r"(a[0]), "r"(a[1]), "r"(a[2]), "r"(a[3]), "r"(b[0]), "r"(b[1]));
}
__device__ __forceinline__ void cp_async16(uint32_t dst, const void* src) {
    asm volatile("cp.async.cg.shared.global [%0], [%1], 16;\n" :: "r"(dst), "l"(src));
}
__device__ __forceinline__ uint32_t smem_u32(const void* p) {
    uint32_t a;
    asm("{ .reg .u64 t; cvta.to.shared.u64 t, %1; cvt.u32.u64 %0, t; }" : "=r"(a) : "l"(p));
    return a;
}

// ---------------- pre-split TF32 NT GEMM, chunk-drained accumulation ---------
// C[m,n] = sum_k A[m,k]*B[n,k]; A,B are float2{t0,t1} planes (pre-split).
// Products {00,10,01}; per-BK32 chunk drained into fp32 master with RNE adds.
// MODE 0: store fp32.  MODE 1: store split float2 planes.
#define BM   128
#define BN   128
#define BKF  32
#define ROW2 36                        // padded row stride in float2 (288 B)
#define TILE2 (128*ROW2)               // float2 per tile
#define SMEM_BYTES (4*TILE2*8)         // A0,B0,A1,B1 = 147456 B

template<int MODE>
__global__ __launch_bounds__(256, 1) void gemm_ps(
    const float2* __restrict__ A, long long batchA, int lda,
    const float2* __restrict__ B, long long batchB, int ldb,
    float* __restrict__ Cf, float2* __restrict__ C2,
    long long batchC, int ldc, int K)
{
    extern __shared__ float2 sm2[];
    float2* const bufA[2] = { sm2,             sm2 + 2 * TILE2 };
    float2* const bufB[2] = { sm2 + TILE2,     sm2 + 3 * TILE2 };

    const int tid  = threadIdx.x;
    const int wid  = tid >> 5;
    const int lane = tid & 31;
    const int gid  = lane >> 2;
    const int t4   = lane & 3;
    const int m_w  = (wid & 1) * 64;
    const int n_w  = (wid >> 1) * 32;
    const int bm   = blockIdx.y * BM;
    const int bn   = blockIdx.x * BN;

    const float2* Ab = A + (long long)blockIdx.z * batchA;
    const float2* Bb = B + (long long)blockIdx.z * batchB;

    auto load_tile = [&](int kt, int st) {
        const int k0 = kt * BKF;
        const uint32_t da = smem_u32(bufA[st]);
        const uint32_t db = smem_u32(bufB[st]);
        // per tile: 128 rows x 16 chunks of 16B (2 float2)
        #pragma unroll
        for (int i = 0; i < 8; ++i) {
            int c = tid + (i << 8);       // 0..2047
            int r = c >> 4;
            int j = (c & 15) << 1;        // float2 col: 0,2,...,30
            cp_async16(da + (r * ROW2 + j) * 8, Ab + (size_t)(bm + r) * lda + k0 + j);
            cp_async16(db + (r * ROW2 + j) * 8, Bb + (size_t)(bn + r) * ldb + k0 + j);
        }
        asm volatile("cp.async.commit_group;\n" ::: "memory");
    };

    float acc_hi[4][4][4] = {};
    float acc[4][4][4] = {};
    const int NK = K / BKF;

    load_tile(0, 0);

    for (int kt = 0; kt < NK; ++kt) {
        if (kt + 1 < NK) {
            load_tile(kt + 1, (kt + 1) & 1);
            asm volatile("cp.async.wait_group 1;\n" ::: "memory");
        } else {
            asm volatile("cp.async.wait_group 0;\n" ::: "memory");
        }
        __syncthreads();

        const float2* As = bufA[kt & 1];
        const float2* Bs = bufB[kt & 1];

        #pragma unroll
        for (int kk = 0; kk < BKF; kk += 8) {
            uint32_t a0[4][4], a1[4][4];
            #pragma unroll
            for (int am = 0; am < 4; ++am) {
                const int r0 = m_w + am * 16 + gid;
                float2 p0 = As[(r0    ) * ROW2 + kk + t4];
                float2 p1 = As[(r0 + 8) * ROW2 + kk + t4];
                float2 p2 = As[(r0    ) * ROW2 + kk + t4 + 4];
                float2 p3 = As[(r0 + 8) * ROW2 + kk + t4 + 4];
                a0[am][0] = __float_as_uint(p0.x); a1[am][0] = __float_as_uint(p0.y);
                a0[am][1] = __float_as_uint(p1.x); a1[am][1] = __float_as_uint(p1.y);
                a0[am][2] = __float_as_uint(p2.x); a1[am][2] = __float_as_uint(p2.y);
                a0[am][3] = __float_as_uint(p3.x); a1[am][3] = __float_as_uint(p3.y);
            }
            uint32_t b0[4][2], b1[4][2];
            #pragma unroll
            for (int an = 0; an < 4; ++an) {
                const int c0 = n_w + an * 8 + gid;
                float2 q0 = Bs[c0 * ROW2 + kk + t4];
                float2 q1 = Bs[c0 * ROW2 + kk + t4 + 4];
                b0[an][0] = __float_as_uint(q0.x); b1[an][0] = __float_as_uint(q0.y);
                b0[an][1] = __float_as_uint(q1.x); b1[an][1] = __float_as_uint(q1.y);
            }
            #pragma unroll
            for (int am = 0; am < 4; ++am)
                #pragma unroll
                for (int an = 0; an < 4; ++an) {
                    mma_tf32(acc[am][an], a0[am], b0[an]);
                    mma_tf32(acc[am][an], a1[am], b0[an]);
                    mma_tf32(acc[am][an], a0[am], b1[an]);
                }
        }

        // drain chunk accumulator into master with RNE adds (kills RZ bias)
        #pragma unroll
        for (int am = 0; am < 4; ++am)
            #pragma unroll
            for (int an = 0; an < 4; ++an)
                #pragma unroll
                for (int i = 0; i < 4; ++i) {
                    acc_hi[am][an][i] += acc[am][an][i];
                    acc[am][an][i] = 0.f;
                }

        __syncthreads();
    }

    #pragma unroll
    for (int am = 0; am < 4; ++am) {
        const int r0 = bm + m_w + am * 16 + gid;
        #pragma unroll
        for (int an = 0; an < 4; ++an) {
            const int cc = bn + n_w + an * 8 + 2 * t4;
            if (MODE == 0) {
                float* Cb = Cf + (long long)blockIdx.z * batchC;
                *(float2*)&Cb[(size_t)(r0    ) * ldc + cc] = make_float2(acc_hi[am][an][0], acc_hi[am][an][1]);
                *(float2*)&Cb[(size_t)(r0 + 8) * ldc + cc] = make_float2(acc_hi[am][an][2], acc_hi[am][an][3]);
            } else {
                float2* Cb = C2 + (long long)blockIdx.z * batchC;
                float2 s0 = split2(acc_hi[am][an][0]);
                float2 s1 = split2(acc_hi[am][an][1]);
                float2 s2 = split2(acc_hi[am][an][2]);
                float2 s3 = split2(acc_hi[am][an][3]);
                *(float4*)&Cb[(size_t)(r0    ) * ldc + cc] = make_float4(s0.x, s0.y, s1.x, s1.y);
                *(float4*)&Cb[(size_t)(r0 + 8) * ldc + cc] = make_float4(s2.x, s2.y, s3.x, s3.y);
            }
        }
    }
}

// ---------------- elementwise split of fp32 tensor into float2{t0,t1} --------
__global__ __launch_bounds__(256) void split_input(const float* __restrict__ x,
                                                   float2* __restrict__ o, size_t n) {
    size_t i = (size_t)blockIdx.x * 256 + threadIdx.x;
    if (i < n) o[i] = split2(x[i]);
}

// ---------------- softmax over q (rows of P[n][k][:]) + /D ----------------
__global__ __launch_bounds__(256) void softmax_div(float* __restrict__ P)
{
    float* p = P + (size_t)blockIdx.x * S;
    const int tid  = threadIdx.x;
    const int lane = tid & 31;
    const int wid  = tid >> 5;

    float v[8];
    float mx = -3.4e38f;
    #pragma unroll
    for (int i = 0; i < 8; ++i) { v[i] = p[tid + (i << 8)]; mx = fmaxf(mx, v[i]); }
    #pragma unroll
    for (int o = 16; o > 0; o >>= 1) mx = fmaxf(mx, __shfl_xor_sync(0xffffffffu, mx, o));

    __shared__ float smax[8], ssum[8];
    if (lane == 0) smax[wid] = mx;
    __syncthreads();
    mx = smax[0];
    #pragma unroll
    for (int w = 1; w < 8; ++w) mx = fmaxf(mx, smax[w]);

    float s = 0.f;
    #pragma unroll
    for (int i = 0; i < 8; ++i) { v[i] = expf(v[i] - mx); s += v[i]; }
    #pragma unroll
    for (int o = 16; o > 0; o >>= 1) s += __shfl_xor_sync(0xffffffffu, s, o);
    if (lane == 0) ssum[wid] = s;
    __syncthreads();
    s = ssum[0];
    #pragma unroll
    for (int w = 1; w < 8; ++w) s += ssum[w];

    const float inv = 1.0f / (s * (float)D);
    #pragma unroll
    for (int i = 0; i < 8; ++i) p[tid + (i << 8)] = v[i] * inv;
}

// ---------------- transpose P[n][k][q] -> Pt[n][q][k], split ----------------
__global__ __launch_bounds__(256) void transpose_split(const float* __restrict__ P,
                                                       float2* __restrict__ Pt)
{
    __shared__ float ts[32][33];
    const int z  = blockIdx.z;
    const int qb = blockIdx.x * 32;
    const int kb = blockIdx.y * 32;
    const int tx = threadIdx.x;
    const int ty = threadIdx.y;
    const float* p = P  + (size_t)z * S * S;
    float2*      o = Pt + (size_t)z * S * S;

    #pragma unroll
    for (int i = 0; i < 4; ++i)
        ts[ty + i * 8][tx] = p[(size_t)(kb + ty + i * 8) * S + qb + tx];
    __syncthreads();
    #pragma unroll
    for (int i = 0; i < 4; ++i)
        o[(size_t)(qb + ty + i * 8) * S + kb + tx] = split2(ts[tx][ty + i * 8]);
}

// ---------------- launch ----------------
extern "C" void kernel_launch(void* const* d_in, const int* in_sizes, int n_in,
                              void* d_out, int out_size)
{
    (void)in_sizes; (void)n_in; (void)out_size;
    const float* v  = (const float*)d_in[0];
    const float* k  = (const float*)d_in[1];
    const float* q  = (const float*)d_in[2];
    const float* WV = (const float*)d_in[3];
    const float* WQ = (const float*)d_in[4];
    const float* WK = (const float*)d_in[5];
    float* out = (float*)d_out;

    float2 *qs, *ks, *vs, *wqw, *wkw, *wvw, *wqs, *wks, *wvts, *pts;
    float *p;
    cudaGetSymbolAddress((void**)&qs,   g_qs);
    cudaGetSymbolAddress((void**)&ks,   g_ks);
    cudaGetSymbolAddress((void**)&vs,   g_vs);
    cudaGetSymbolAddress((void**)&wqw,  g_wqw);
    cudaGetSymbolAddress((void**)&wkw,  g_wkw);
    cudaGetSymbolAddress((void**)&wvw,  g_wvw);
    cudaGetSymbolAddress((void**)&wqs,  g_wqs);
    cudaGetSymbolAddress((void**)&wks,  g_wks);
    cudaGetSymbolAddress((void**)&wvts, g_wvts);
    cudaGetSymbolAddress((void**)&p,    g_p);
    cudaGetSymbolAddress((void**)&pts,  g_pts);

    cudaFuncSetAttribute(gemm_ps<0>, cudaFuncAttributeMaxDynamicSharedMemorySize, SMEM_BYTES);
    cudaFuncSetAttribute(gemm_ps<1>, cudaFuncAttributeMaxDynamicSharedMemorySize, SMEM_BYTES);

    const size_t nBig = (size_t)NS * D;
    const size_t nW   = (size_t)D * D;
    const dim3 blk(256);

    split_input<<<(unsigned)((nBig + 255) / 256), 256>>>(q,  qs,  nBig);
    split_input<<<(unsigned)((nBig + 255) / 256), 256>>>(k,  ks,  nBig);
    split_input<<<(unsigned)((nBig + 255) / 256), 256>>>(v,  vs,  nBig);
    split_input<<<(unsigned)((nW  + 255) / 256), 256>>>(WQ, wqw, nW);
    split_input<<<(unsigned)((nW  + 255) / 256), 256>>>(WK, wkw, nW);
    split_input<<<(unsigned)((nW  + 255) / 256), 256>>>(WV, wvw, nW);

    // wq = q @ WQ^T   [NS, D]  -> split planes
    gemm_ps<1><<<dim3(D / BN, NS / BM, 1), blk, SMEM_BYTES>>>(
        qs, 0, D, wqw, 0, D, nullptr, wqs, 0, D, D);
    // wk = k @ WK^T   [NS, D]  -> split planes
    gemm_ps<1><<<dim3(D / BN, NS / BM, 1), blk, SMEM_BYTES>>>(
        ks, 0, D, wkw, 0, D, nullptr, wks, 0, D, D);
    // wvT = WV @ v^T  [D, NS]  -> split planes
    gemm_ps<1><<<dim3(NS / BN, D / BM, 1), blk, SMEM_BYTES>>>(
        wvw, 0, D, vs, 0, D, nullptr, wvts, 0, NS, D);
    // scores P[n][k][q] = wk @ wq^T per batch  [S, S]  -> fp32
    gemm_ps<0><<<dim3(S / BN, S / BM, NB), blk, SMEM_BYTES>>>(
        wks, (long long)S * D, D, wqs, (long long)S * D, D,
        p, nullptr, (long long)S * S, S, D);
    // softmax over q (rows) + /D
    softmax_div<<<NB * S, 256>>>(p);
    // transpose + split: Pt[n][q][k]
    transpose_split<<<dim3(S / 32, S / 32, NB), dim3(32, 8)>>>(p, pts);
    // out[n][q][o] = Pt @ wvT^T per batch  [S, D], K = S  -> fp32
    gemm_ps<0><<<dim3(D / BN, S / BM, NB), blk, SMEM_BYTES>>>(
        pts, (long long)S * S, S, wvts, (long long)S, NS,
        out, nullptr, (long long)S * D, D, S);
}

// round 10
// speedup vs baseline: 3.5891x; 3.5891x over previous
#include <cuda_runtime.h>
#include <cuda_fp16.h>
#include <cstdint>
#include <math.h>

#define NB   4
#define S    2048
#define D    1024
#define NS   (NB*S)               // 8192

// ---------------- device scratch: fp16 split planes --------------------------
// Each tensor stored as 2 planes of fp16-pairs (uint32 = half2 of consecutive k).
// plane stride = rows * K/2 words.
__device__ uint32_t g_qs  [(size_t)NS*D];     // q     split  (2 x NS x D/2)
__device__ uint32_t g_ks  [(size_t)NS*D];     // k     split
__device__ uint32_t g_vs  [(size_t)NS*D];     // v     split
__device__ uint32_t g_wqw [(size_t)D*D];      // WQ    split
__device__ uint32_t g_wkw [(size_t)D*D];      // WK    split
__device__ uint32_t g_wvw [(size_t)D*D];      // WV    split
__device__ uint32_t g_wqs [(size_t)NS*D];     // wq  proj split
__device__ uint32_t g_wks [(size_t)NS*D];     // wk  proj split
__device__ uint32_t g_wvts[(size_t)D*NS];     // wv^T proj split [o][ns]
__device__ float    g_p   [(size_t)NB*S*S];   // scores P[n][k][q] fp32
__device__ uint32_t g_pts [(size_t)NB*S*S];   // softmaxed P^T split [n][q][k/2]

// ---------------- helpers ----------------
__device__ __forceinline__ void split_h(float f, __half& h0, __half& h1) {
    h0 = __float2half_rn(f);
    h1 = __float2half_rn(f - __half2float(h0));
}
__device__ __forceinline__ uint32_t packh(__half a, __half b) {
    __half2 h = __halves2half2(a, b);
    return *reinterpret_cast<uint32_t*>(&h);
}
__device__ __forceinline__ void mma_h(float* c, const uint32_t* a, const uint32_t* b) {
    asm volatile(
        "mma.sync.aligned.m16n8k16.row.col.f32.f16.f16.f32 "
        "{%0,%1,%2,%3}, {%4,%5,%6,%7}, {%8,%9}, {%0,%1,%2,%3};"
        : "+f"(c[0]), "+f"(c[1]), "+f"(c[2]), "+f"(c[3])
        : "r"(a[0]), "r"(a[1]), "r"(a[2]), "r"(a[3]), "r"(b[0]), "r"(b[1]));
}
__device__ __forceinline__ void cp_async16(uint32_t dst, const void* src) {
    asm volatile("cp.async.cg.shared.global [%0], [%1], 16;\n" :: "r"(dst), "l"(src));
}
__device__ __forceinline__ uint32_t smem_u32(const void* p) {
    uint32_t a;
    asm("{ .reg .u64 t; cvta.to.shared.u64 t, %1; cvt.u32.u64 %0, t; }" : "=r"(a) : "l"(p));
    return a;
}

// ---------------- fp16x2-split NT GEMM, chunk-drained accumulation -----------
// C[m,n] = sum_k A[m,k]*B[n,k]; A,B given as 2 fp16 planes of half2 words.
// Products {h0h0, h1h0, h0h1} via mma.m16n8k16; drained every BK=64 into fp32
// master with RNE adds (suppresses tensor-core RZ accumulation bias).
#define BM    128
#define BN    128
#define BKW   32                    // words per row per chunk (= 64 k)
#define ROWW  36                    // padded row stride in words (144 B)
#define TILEW (128*ROWW)            // words per tile (A0/A1/B0/B1)
#define STAGEW (4*TILEW)
#define SMEM_BYTES (2*STAGEW*4)     // 147456 B

template<int MODE>    // 0: fp32 out, 1: split fp16-plane out
__global__ __launch_bounds__(256, 1) void gemm_h2(
    const uint32_t* __restrict__ A, long long planeA, long long batchA, int lda,
    const uint32_t* __restrict__ B, long long planeB, long long batchB, int ldb,
    float* __restrict__ Cf, uint32_t* __restrict__ C2,
    long long planeC, long long batchC, int ldc, int K)
{
    extern __shared__ uint32_t smw[];
    const uint32_t sb = smem_u32(smw);

    const int tid  = threadIdx.x;
    const int wid  = tid >> 5;
    const int lane = tid & 31;
    const int gid  = lane >> 2;
    const int t4   = lane & 3;
    const int m_w  = (wid & 1) * 64;
    const int n_w  = (wid >> 1) * 32;
    const int bm   = blockIdx.y * BM;
    const int bn   = blockIdx.x * BN;

    const uint32_t* Ab = A + (long long)blockIdx.z * batchA;
    const uint32_t* Bb = B + (long long)blockIdx.z * batchB;

    auto load_tile = [&](int kt, int st) {
        const int k0w = kt * BKW;
        #pragma unroll
        for (int i = 0; i < 16; ++i) {
            int idx  = tid + (i << 8);        // 0..4095
            int tile = idx >> 10;             // 0..3 : A0,A1,B0,B1
            int r    = (idx >> 3) & 127;
            int j    = idx & 7;               // 16B chunk (4 words)
            const uint32_t* src;
            if (tile < 2) src = Ab + (long long)tile * planeA + (size_t)(bm + r) * lda + k0w + j * 4;
            else          src = Bb + (long long)(tile - 2) * planeB + (size_t)(bn + r) * ldb + k0w + j * 4;
            uint32_t dst = sb + 4u * (st * STAGEW + tile * TILEW + r * ROWW + j * 4);
            cp_async16(dst, src);
        }
        asm volatile("cp.async.commit_group;\n" ::: "memory");
    };

    float acc_hi[4][4][4] = {};
    float acc[4][4][4] = {};
    const int NK = K / 64;

    load_tile(0, 0);

    for (int kt = 0; kt < NK; ++kt) {
        if (kt + 1 < NK) {
            load_tile(kt + 1, (kt + 1) & 1);
            asm volatile("cp.async.wait_group 1;\n" ::: "memory");
        } else {
            asm volatile("cp.async.wait_group 0;\n" ::: "memory");
        }
        __syncthreads();

        const uint32_t* A0 = smw + (kt & 1) * STAGEW;
        const uint32_t* A1 = A0 + TILEW;
        const uint32_t* B0 = A0 + 2 * TILEW;
        const uint32_t* B1 = A0 + 3 * TILEW;

        #pragma unroll
        for (int ks = 0; ks < 4; ++ks) {        // 4 x k16 per BK64
            const int w0 = ks * 8;
            uint32_t fa0[4][4], fa1[4][4];
            #pragma unroll
            for (int am = 0; am < 4; ++am) {
                const int r0 = (m_w + am * 16 + gid) * ROWW + w0 + t4;
                const int r1 = r0 + 8 * ROWW;
                fa0[am][0] = A0[r0];     fa0[am][1] = A0[r1];
                fa0[am][2] = A0[r0 + 4]; fa0[am][3] = A0[r1 + 4];
                fa1[am][0] = A1[r0];     fa1[am][1] = A1[r1];
                fa1[am][2] = A1[r0 + 4]; fa1[am][3] = A1[r1 + 4];
            }
            uint32_t fb0[4][2], fb1[4][2];
            #pragma unroll
            for (int an = 0; an < 4; ++an) {
                const int c0 = (n_w + an * 8 + gid) * ROWW + w0 + t4;
                fb0[an][0] = B0[c0]; fb0[an][1] = B0[c0 + 4];
                fb1[an][0] = B1[c0]; fb1[an][1] = B1[c0 + 4];
            }
            #pragma unroll
            for (int am = 0; am < 4; ++am)
                #pragma unroll
                for (int an = 0; an < 4; ++an) {
                    mma_h(acc[am][an], fa0[am], fb0[an]);
                    mma_h(acc[am][an], fa1[am], fb0[an]);
                    mma_h(acc[am][an], fa0[am], fb1[an]);
                }
        }

        // drain chunk accumulator into master with RNE adds (kills RZ bias)
        #pragma unroll
        for (int am = 0; am < 4; ++am)
            #pragma unroll
            for (int an = 0; an < 4; ++an)
                #pragma unroll
                for (int i = 0; i < 4; ++i) {
                    acc_hi[am][an][i] += acc[am][an][i];
                    acc[am][an][i] = 0.f;
                }

        __syncthreads();
    }

    #pragma unroll
    for (int am = 0; am < 4; ++am) {
        const int r0 = bm + m_w + am * 16 + gid;
        #pragma unroll
        for (int an = 0; an < 4; ++an) {
            if (MODE == 0) {
                const int cc = bn + n_w + an * 8 + 2 * t4;
                float* Cb = Cf + (long long)blockIdx.z * batchC;
                *(float2*)&Cb[(size_t)(r0    ) * ldc + cc] = make_float2(acc_hi[am][an][0], acc_hi[am][an][1]);
                *(float2*)&Cb[(size_t)(r0 + 8) * ldc + cc] = make_float2(acc_hi[am][an][2], acc_hi[am][an][3]);
            } else {
                const int wc = (bn + n_w + an * 8) / 2 + t4;
                uint32_t* Cb = C2 + (long long)blockIdx.z * batchC;
                __half h0a, h1a, h0b, h1b;
                split_h(acc_hi[am][an][0], h0a, h1a);
                split_h(acc_hi[am][an][1], h0b, h1b);
                Cb[(size_t)(r0) * ldc + wc]          = packh(h0a, h0b);
                Cb[planeC + (size_t)(r0) * ldc + wc] = packh(h1a, h1b);
                split_h(acc_hi[am][an][2], h0a, h1a);
                split_h(acc_hi[am][an][3], h0b, h1b);
                Cb[(size_t)(r0 + 8) * ldc + wc]          = packh(h0a, h0b);
                Cb[planeC + (size_t)(r0 + 8) * ldc + wc] = packh(h1a, h1b);
            }
        }
    }
}

// ---------------- split two fp32 tensors into fp16 planes (pairs) ------------
__global__ __launch_bounds__(256) void split_two(
    const float* __restrict__ x0, uint32_t* __restrict__ o0, size_t np0,
    const float* __restrict__ x1, uint32_t* __restrict__ o1, size_t np1)
{
    size_t nb0 = (np0 + 255) / 256;
    const float* x; uint32_t* o; size_t i, np;
    if (blockIdx.x < nb0) { x = x0; o = o0; np = np0; i = (size_t)blockIdx.x * 256 + threadIdx.x; }
    else { x = x1; o = o1; np = np1; i = (size_t)(blockIdx.x - nb0) * 256 + threadIdx.x; }
    if (i >= np) return;
    float f0 = x[2 * i], f1 = x[2 * i + 1];
    __half a0, a1, b0, b1;
    split_h(f0, a0, a1);
    split_h(f1, b0, b1);
    o[i]       = packh(a0, b0);
    o[np + i]  = packh(a1, b1);
}

// ---------------- softmax over q (rows of P[n][k][:]) + /D ----------------
__global__ __launch_bounds__(256) void softmax_div(float* __restrict__ P)
{
    float* p = P + (size_t)blockIdx.x * S;
    const int tid  = threadIdx.x;
    const int lane = tid & 31;
    const int wid  = tid >> 5;

    float v[8];
    float mx = -3.4e38f;
    #pragma unroll
    for (int i = 0; i < 8; ++i) { v[i] = p[tid + (i << 8)]; mx = fmaxf(mx, v[i]); }
    #pragma unroll
    for (int o = 16; o > 0; o >>= 1) mx = fmaxf(mx, __shfl_xor_sync(0xffffffffu, mx, o));

    __shared__ float smax[8], ssum[8];
    if (lane == 0) smax[wid] = mx;
    __syncthreads();
    mx = smax[0];
    #pragma unroll
    for (int w = 1; w < 8; ++w) mx = fmaxf(mx, smax[w]);

    float s = 0.f;
    #pragma unroll
    for (int i = 0; i < 8; ++i) { v[i] = expf(v[i] - mx); s += v[i]; }
    #pragma unroll
    for (int o = 16; o > 0; o >>= 1) s += __shfl_xor_sync(0xffffffffu, s, o);
    if (lane == 0) ssum[wid] = s;
    __syncthreads();
    s = ssum[0];
    #pragma unroll
    for (int w = 1; w < 8; ++w) s += ssum[w];

    const float inv = 1.0f / (s * (float)D);
    #pragma unroll
    for (int i = 0; i < 8; ++i) p[tid + (i << 8)] = v[i] * inv;
}

// ---------------- transpose P[n][k][q] -> Pt[n][q][k], split to fp16 planes --
__global__ __launch_bounds__(256) void transpose_split(const float* __restrict__ P,
                                                       uint32_t* __restrict__ Pt)
{
    __shared__ float ts[32][33];
    const int z  = blockIdx.z;
    const int qb = blockIdx.x * 32;
    const int kb = blockIdx.y * 32;
    const int tx = threadIdx.x;
    const int ty = threadIdx.y;
    const float* p = P + (size_t)z * S * S;
    const size_t plane = (size_t)NB * S * (S / 2);
    uint32_t* o = Pt + (size_t)z * S * (S / 2);

    #pragma unroll
    for (int i = 0; i < 4; ++i)
        ts[ty + i * 8][tx] = p[(size_t)(kb + ty + i * 8) * S + qb + tx];
    __syncthreads();

    if (tx < 16) {
        #pragma unroll
        for (int i = 0; i < 4; ++i) {
            const int qq = ty + i * 8;
            float f0 = ts[2 * tx][qq];
            float f1 = ts[2 * tx + 1][qq];
            __half a0, a1, b0, b1;
            split_h(f0, a0, a1);
            split_h(f1, b0, b1);
            size_t off = (size_t)(qb + qq) * (S / 2) + kb / 2 + tx;
            o[off]         = packh(a0, b0);
            o[plane + off] = packh(a1, b1);
        }
    }
}

// ---------------- launch ----------------
extern "C" void kernel_launch(void* const* d_in, const int* in_sizes, int n_in,
                              void* d_out, int out_size)
{
    (void)in_sizes; (void)n_in; (void)out_size;
    const float* v  = (const float*)d_in[0];
    const float* k  = (const float*)d_in[1];
    const float* q  = (const float*)d_in[2];
    const float* WV = (const float*)d_in[3];
    const float* WQ = (const float*)d_in[4];
    const float* WK = (const float*)d_in[5];
    float* out = (float*)d_out;

    uint32_t *qs, *ks, *vs, *wqw, *wkw, *wvw, *wqs, *wks, *wvts, *pts;
    float *p;
    cudaGetSymbolAddress((void**)&qs,   g_qs);
    cudaGetSymbolAddress((void**)&ks,   g_ks);
    cudaGetSymbolAddress((void**)&vs,   g_vs);
    cudaGetSymbolAddress((void**)&wqw,  g_wqw);
    cudaGetSymbolAddress((void**)&wkw,  g_wkw);
    cudaGetSymbolAddress((void**)&wvw,  g_wvw);
    cudaGetSymbolAddress((void**)&wqs,  g_wqs);
    cudaGetSymbolAddress((void**)&wks,  g_wks);
    cudaGetSymbolAddress((void**)&wvts, g_wvts);
    cudaGetSymbolAddress((void**)&p,    g_p);
    cudaGetSymbolAddress((void**)&pts,  g_pts);

    cudaFuncSetAttribute(gemm_h2<0>, cudaFuncAttributeMaxDynamicSharedMemorySize, SMEM_BYTES);
    cudaFuncSetAttribute(gemm_h2<1>, cudaFuncAttributeMaxDynamicSharedMemorySize, SMEM_BYTES);

    const size_t pBig = (size_t)NS * D / 2;   // pairs in big tensors
    const size_t pW   = (size_t)D * D / 2;    // pairs in weights
    const long long plBig = (long long)pBig;  // plane stride words
    const long long plW   = (long long)pW;
    const dim3 blk(256);

    unsigned nbBig = (unsigned)((pBig + 255) / 256);
    unsigned nbW   = (unsigned)((pW   + 255) / 256);

    // launches 1-3: splits (ordered so launch #6 = score GEMM for ncu -s 5)
    split_two<<<nbBig * 2, 256>>>(q, qs, pBig, k, ks, pBig);
    split_two<<<nbW  * 2, 256>>>(WQ, wqw, pW, WK, wkw, pW);
    split_two<<<nbBig + nbW, 256>>>(v, vs, pBig, WV, wvw, pW);

    // 4: wq = q @ WQ^T  [NS, D] -> split planes
    gemm_h2<1><<<dim3(D / BN, NS / BM, 1), blk, SMEM_BYTES>>>(
        qs, plBig, 0, D / 2, wqw, plW, 0, D / 2,
        nullptr, wqs, plBig, 0, D / 2, D);
    // 5: wk = k @ WK^T
    gemm_h2<1><<<dim3(D / BN, NS / BM, 1), blk, SMEM_BYTES>>>(
        ks, plBig, 0, D / 2, wkw, plW, 0, D / 2,
        nullptr, wks, plBig, 0, D / 2, D);
    // 6: scores P[n][k][q] = wk @ wq^T per batch  [S, S] -> fp32  (ncu target)
    gemm_h2<0><<<dim3(S / BN, S / BM, NB), blk, SMEM_BYTES>>>(
        wks, plBig, (long long)S * D / 2, D / 2,
        wqs, plBig, (long long)S * D / 2, D / 2,
        p, nullptr, 0, (long long)S * S, S, D);
    // 7: wvT = WV @ v^T  [D, NS] -> split planes
    gemm_h2<1><<<dim3(NS / BN, D / BM, 1), blk, SMEM_BYTES>>>(
        wvw, plW, 0, D / 2, vs, plBig, 0, D / 2,
        nullptr, wvts, (long long)D * NS / 2, 0, NS / 2, D);
    // 8: softmax over q (rows) + /D
    softmax_div<<<NB * S, 256>>>(p);
    // 9: transpose + split: Pt[n][q][k]
    transpose_split<<<dim3(S / 32, S / 32, NB), dim3(32, 8)>>>(p, pts);
    // 10: out[n][q][o] = Pt @ wvT^T per batch  [S, D], K = S -> fp32
    gemm_h2<0><<<dim3(D / BN, S / BM, NB), blk, SMEM_BYTES>>>(
        pts, (long long)NB * S * S / 2, (long long)S * S / 2, S / 2,
        wvts, (long long)D * NS / 2, (long long)S / 2, NS / 2,
        out, nullptr, 0, (long long)S * D, D, S);
}